// round 13
// baseline (speedup 1.0000x reference)
#include <cuda_runtime.h>
#include <cuda_bf16.h>
#include <cstdint>

// Problem dims (fixed)
#define BATCH 256
#define TSEQ  512
#define DDIM  128
#define ND3   384   // 3*D
#define NC    768   // combined output cols (Wa | Wb)
#define TD    65536 // TSEQ*DDIM (one sample of states)

// dynamic smem for the two wide-tile GEMMs: A/H [32][66] float2 + B [32][130] float2
#define GEMM_SMEM ((32 * 66 + 32 * 130) * 8)   // 50176 B
// dynamic smem for k_gru: Usm[16][384] float2 (last 16 k-pairs of U)
#define GRU_SMEM  (16 * 384 * 8)               // 49152 B

// ---------------- scratch (static device arrays; no allocations) ----------------
__device__ float g_xpc[(size_t)BATCH * TSEQ * NC];  // [b][tau][768] natural-order proj
__device__ float g_g[(size_t)BATCH * TSEQ * DDIM];  // GRU a states [b][t][d]
__device__ float g_h[(size_t)BATCH * TSEQ * DDIM];  // GRU b states [b][t][d]
__device__ float g_alpha[(size_t)BATCH * TSEQ];     // softmax weights
__device__ int   g_perm[BATCH];                     // descending-length permutation

typedef unsigned long long ull;

__device__ __forceinline__ void ffma2(ull &d, ull a, ull b) {
    asm("fma.rn.f32x2 %0, %1, %2, %0;" : "+l"(d) : "l"(a), "l"(b));
}
__device__ __forceinline__ ull pk2(float lo, float hi) {
    ull r; asm("mov.b64 %0, {%1,%2};" : "=l"(r) : "f"(lo), "f"(hi)); return r;
}
__device__ __forceinline__ float2 upk2(ull v) {
    float lo, hi; asm("mov.b64 {%0,%1}, %2;" : "=f"(lo), "=f"(hi) : "l"(v));
    return make_float2(lo, hi);
}
__device__ __forceinline__ float sigm(float v) { return 1.f / (1.f + __expf(-v)); }
__device__ __forceinline__ float ftanh(float y) {
    float e = __expf(2.f * y);
    return 1.f - 2.f / (e + 1.f);
}
__device__ __forceinline__ unsigned sptr(const void* p) {
    return (unsigned)__cvta_generic_to_shared(p);
}
__device__ __forceinline__ void cp8(unsigned dst, const void* src) {
    asm volatile("cp.async.ca.shared.global [%0], [%1], 8;" :: "r"(dst), "l"(src));
}
#define CP_COMMIT() asm volatile("cp.async.commit_group;")
#define CP_WAIT1()  asm volatile("cp.async.wait_group 1;")
#define CP_WAIT0()  asm volatile("cp.async.wait_group 0;")

// ============================================================================
// Kernel 0: descending rank-sort of lengths -> g_perm (O(B^2), one block)
// ============================================================================
__global__ void __launch_bounds__(BATCH) k_sort(const int* __restrict__ lengths)
{
    __shared__ int ls[BATCH];
    const int i = threadIdx.x;
    ls[i] = lengths[i];
    __syncthreads();
    const int li = ls[i];
    int r = 0;
#pragma unroll 8
    for (int j = 0; j < BATCH; ++j) {
        int lj = ls[j];
        r += (lj > li) || (lj == li && j < i);
    }
    g_perm[r] = i;
}

// ============================================================================
// Kernel 1: projection, 64 tau x 128 col tiles (dynamic smem 50.2 KB).
// ============================================================================
__global__ void __launch_bounds__(256) k_xp(
    const float* __restrict__ x, const int* __restrict__ lengths,
    const float* __restrict__ Wa, const float* __restrict__ ba,
    const float* __restrict__ Wb, const float* __restrict__ bb)
{
    const int rt   = blockIdx.x;
    const int b    = rt >> 3;
    const int tau0 = (rt & 7) << 6;
    const int len  = lengths[b];
    if (tau0 >= len) return;            // dead tile

    extern __shared__ __align__(16) char smbuf[];
    float2* As2 = (float2*)smbuf;                    // [32][66]  k-paired A
    float2* Bs2 = (float2*)(smbuf + 32 * 66 * 8);    // [32][130] k-paired B

    const int c0 = blockIdx.y << 7;
    const float* W    = (c0 < ND3) ? Wa : Wb;
    const float* bias = (c0 < ND3) ? ba : bb;
    const int cw = (c0 < ND3) ? c0 : (c0 - ND3);

    const int tid  = threadIdx.x;
    const int w    = tid >> 5, lane = tid & 31;
    const int txp  = ((w & 1) << 3) + (lane & 7);
    const int typ  = ((w >> 1) << 2) + (lane >> 3);

    ull acc[4][8];
#pragma unroll
    for (int i = 0; i < 4; i++)
#pragma unroll
        for (int j = 0; j < 8; j++) acc[i][j] = 0ull;

    for (int kc = 0; kc < 2; ++kc) {
        __syncthreads();
#pragma unroll
        for (int l = 0; l < 16; ++l) {
            int idx = tid + l * 256;
            int tt = idx >> 6, kk = idx & 63;
            float v = x[((size_t)b * TSEQ + tau0 + tt) * DDIM + kc * 64 + kk];
            ((float*)(As2 + (kk >> 1) * 66 + tt))[kk & 1] = v;
        }
#pragma unroll
        for (int l = 0; l < 32; ++l) {
            int idx = tid + l * 256;
            int kk = idx >> 7, jj = idx & 127;
            float wv = W[(size_t)(kc * 64 + kk) * ND3 + cw + jj];
            ((float*)(Bs2 + (kk >> 1) * 130 + jj))[kk & 1] = wv;
        }
        __syncthreads();
#pragma unroll 4
        for (int q = 0; q < 32; ++q) {
            ulonglong2 a0 = *(const ulonglong2*)(As2 + q * 66 + 4 * typ);
            ulonglong2 a1 = *(const ulonglong2*)(As2 + q * 66 + 4 * typ + 2);
            ulonglong2 b0 = *(const ulonglong2*)(Bs2 + q * 130 + 4 * txp);
            ulonglong2 b1 = *(const ulonglong2*)(Bs2 + q * 130 + 4 * txp + 2);
            ulonglong2 b2 = *(const ulonglong2*)(Bs2 + q * 130 + 64 + 4 * txp);
            ulonglong2 b3 = *(const ulonglong2*)(Bs2 + q * 130 + 64 + 4 * txp + 2);
            ull av[4] = { a0.x, a0.y, a1.x, a1.y };
            ull bv[8] = { b0.x, b0.y, b1.x, b1.y, b2.x, b2.y, b3.x, b3.y };
#pragma unroll
            for (int i = 0; i < 4; i++)
#pragma unroll
                for (int j = 0; j < 8; j++)
                    ffma2(acc[i][j], av[i], bv[j]);
        }
    }
#pragma unroll
    for (int i = 0; i < 4; i++) {
        int tau = tau0 + 4 * typ + i;
        float* orow = &g_xpc[((size_t)b * TSEQ + tau) * NC + c0];
        float4 o0, o1;
        float* p0 = (float*)&o0;
        float* p1 = (float*)&o1;
#pragma unroll
        for (int j = 0; j < 4; j++) {
            float2 f = upk2(acc[i][j]);
            p0[j] = f.x + f.y + bias[cw + 4 * txp + j];
        }
#pragma unroll
        for (int j = 0; j < 4; j++) {
            float2 f = upk2(acc[i][4 + j]);
            p1[j] = f.x + f.y + bias[cw + 64 + 4 * txp + j];
        }
        *(float4*)&orow[4 * txp]      = o0;
        *(float4*)&orow[64 + 4 * txp] = o1;
    }
}

// ============================================================================
// Kernel 2: masked GRU recurrence. Register-budget fix: U column held as
// 48 k-pairs in registers (96 regs, fits the 168 cap => no local demotion)
// + last 16 k-pairs in smem Usm[16][384] (conflict-free float2). Four
// independent accumulator chains. Otherwise identical to the R12 structure.
// ============================================================================
__global__ void __launch_bounds__(384, 1) k_gru(
    const int*   __restrict__ lengths,
    const float* __restrict__ Ua, const float* __restrict__ ba_rec,
    const float* __restrict__ Ub, const float* __restrict__ bb_rec)
{
    __shared__ __align__(16) float hsm[2][DDIM];
    __shared__ float rps[2][ND3];
    __shared__ __align__(16) float xsm[2][2 * ND3];   // [buf][s*384 + c]
    extern __shared__ __align__(16) char gsm[];
    float2* Usm = (float2*)gsm;                        // [16][384] k-pairs 48..63

    const int gru  = (blockIdx.x >= 74) ? 1 : 0;
    const int slot = blockIdx.x - gru * 74;
    const int j    = threadIdx.x;

    const float* U   = gru ? Ub     : Ua;
    const float* brp = gru ? bb_rec : ba_rec;
    float*       st  = gru ? g_h    : g_g;
    const int    coff = gru * ND3;

    // k-pairs 0..47 (k 0..95) in registers
    ull u2[48];
#pragma unroll
    for (int kp = 0; kp < 48; ++kp)
        u2[kp] = pk2(U[(size_t)(2 * kp) * ND3 + j], U[(size_t)(2 * kp + 1) * ND3 + j]);
    // k-pairs 48..63 (k 96..127) in smem
#pragma unroll
    for (int r = 0; r < 16; ++r) {
        float lo = U[(size_t)(96 + 2 * r) * ND3 + j];
        float hi = U[(size_t)(97 + 2 * r) * ND3 + j];
        Usm[r * ND3 + j] = make_float2(lo, hi);
    }
    const float brec = brp[j];

    const int s = (j >> 7) & 1;
    const int d = j & 127;
    const bool gate_th = (j < 256);
    const bool pf_th   = (j >= 256);
    const int  pt      = j - 256;

    for (int pi = 0; pi < 2; ++pi) {
        const int pr = pi ? (147 - slot) : slot;
        if (pr >= 128) continue;

        const int b_s0 = g_perm[2 * pr];
        const int b_s1 = g_perm[2 * pr + 1];
        const int len0 = lengths[b_s0];
        const int len1 = lengths[b_s1];
        const int maxlen = max(len0, len1);
        const int b_g   = s ? b_s1 : b_s0;
        const int len_g = s ? len1 : len0;
        float* stp = st + (size_t)b_g * TD + d;

        for (int idx = j; idx < 2 * DDIM; idx += 384) ((float*)hsm)[idx] = 0.f;

        if (pf_th) {
#pragma unroll
            for (int i = 0; i < 3; ++i) {
                int p  = pt + 128 * i;
                int sp = (p >= 192) ? 1 : 0;
                int c2 = p - sp * 192;
                int bsp = sp ? b_s1 : b_s0;
                int lsp = sp ? len1 : len0;
                const float* gsrc = g_xpc + ((size_t)bsp * TSEQ + (lsp - 1)) * NC + coff + 2 * c2;
                cp8(sptr(&xsm[0][sp * 384 + 2 * c2]), gsrc);
            }
            CP_COMMIT();
            CP_WAIT0();
        }
        __syncthreads();

        for (int t = 0; t < maxlen; ++t) {
            const int buf  = t & 1;
            const bool more = (t + 1 < maxlen);
            if (pf_th && more) {
#pragma unroll
                for (int i = 0; i < 3; ++i) {
                    int p  = pt + 128 * i;
                    int sp = (p >= 192) ? 1 : 0;
                    int c2 = p - sp * 192;
                    int bsp = sp ? b_s1 : b_s0;
                    int lsp = sp ? len1 : len0;
                    if (t + 1 < lsp) {
                        const float* gsrc = g_xpc + ((size_t)bsp * TSEQ + (lsp - 2 - t)) * NC + coff + 2 * c2;
                        cp8(sptr(&xsm[buf ^ 1][sp * 384 + 2 * c2]), gsrc);
                    }
                }
                CP_COMMIT();
            }

            // rp[s][j] = h[s] . U[:,j] + b_rec[j]; 4 chains (2 per sample)
            ull a0A = pk2(brec, 0.f), a0B = 0ull;
            ull a1A = pk2(brec, 0.f), a1B = 0ull;
            // register half: k-pairs 0..47 (k 0..95)
#pragma unroll
            for (int q = 0; q < 24; ++q) {
                ulonglong2 h0 = *(const ulonglong2*)&hsm[0][4 * q];
                ulonglong2 h1 = *(const ulonglong2*)&hsm[1][4 * q];
                ffma2(a0A, u2[2 * q],     h0.x);
                ffma2(a0B, u2[2 * q + 1], h0.y);
                ffma2(a1A, u2[2 * q],     h1.x);
                ffma2(a1B, u2[2 * q + 1], h1.y);
            }
            // smem half: k-pairs 48..63 (k 96..127)
#pragma unroll
            for (int q = 0; q < 8; ++q) {
                ulonglong2 h0 = *(const ulonglong2*)&hsm[0][96 + 4 * q];
                ulonglong2 h1 = *(const ulonglong2*)&hsm[1][96 + 4 * q];
                ull us0 = *(const ull*)&Usm[(2 * q) * ND3 + j];
                ull us1 = *(const ull*)&Usm[(2 * q + 1) * ND3 + j];
                ffma2(a0A, us0, h0.x);
                ffma2(a0B, us1, h0.y);
                ffma2(a1A, us0, h1.x);
                ffma2(a1B, us1, h1.y);
            }
            {
                float2 fA = upk2(a0A), fB = upk2(a0B);
                rps[0][j] = (fA.x + fA.y) + (fB.x + fB.y);
            }
            {
                float2 fA = upk2(a1A), fB = upk2(a1B);
                rps[1][j] = (fA.x + fA.y) + (fB.x + fB.y);
            }

            if (pf_th) { if (more) { CP_WAIT1(); } else { CP_WAIT0(); } }
            __syncthreads();

            if (gate_th) {
                float h_old = hsm[s][d];
                float hn = h_old;
                if (t < len_g) {
                    float xz = xsm[buf][s * 384 + d];
                    float xr = xsm[buf][s * 384 + 128 + d];
                    float xh = xsm[buf][s * 384 + 256 + d];
                    float zg = sigm(xz + rps[s][d]);
                    float rg = sigm(xr + rps[s][128 + d]);
                    float hh = ftanh(xh + rg * rps[s][256 + d]);
                    hn = zg * h_old + (1.f - zg) * hh;
                }
                hsm[s][d] = hn;
                stp[0] = hn;
            }
            __syncthreads();
            stp += DDIM;
        }
        const int tail = TSEQ - maxlen;
        for (int idx = j; idx < tail * 256; idx += 384) {
            int dd = idx & 127;
            int ss = (idx >> 7) & 1;
            int tt = idx >> 8;
            int bb = ss ? b_s1 : b_s0;
            st[(size_t)bb * TD + (size_t)(maxlen + tt) * DDIM + dd] = hsm[ss][dd];
        }
        __syncthreads();
    }
}

// ============================================================================
// Kernel 3a: alpha weights (unchanged); also zeros out for k_beta's atomics.
// ============================================================================
__global__ void __launch_bounds__(128, 4) k_alpha(
    const float* __restrict__ W_alpha, const float* __restrict__ b_alpha,
    float* __restrict__ out)
{
    __shared__ float e_s[TSEQ];
    __shared__ float red[4];
    __shared__ float scal[2];

    const int b    = blockIdx.x;
    const int tid  = threadIdx.x;
    const int lane = tid & 31, w = tid >> 5;

    out[(size_t)b * DDIM + tid] = 0.f;

    float4 wa = *(const float4*)&W_alpha[lane * 4];
    const float b_a = b_alpha[0];
    const float* gbase = g_g + (size_t)b * TD;
    for (int tt = 0; tt < 128; ++tt) {
        int t = tt * 4 + w;
        float4 gv = *(const float4*)&gbase[(size_t)t * DDIM + lane * 4];
        float sum = gv.x * wa.x + gv.y * wa.y + gv.z * wa.z + gv.w * wa.w;
#pragma unroll
        for (int o = 16; o > 0; o >>= 1) sum += __shfl_xor_sync(0xffffffffu, sum, o);
        if (lane == 0) e_s[t] = sum + b_a;
    }
    __syncthreads();

    float m = -1e30f;
    for (int i = tid; i < TSEQ; i += 128) m = fmaxf(m, e_s[i]);
#pragma unroll
    for (int o = 16; o > 0; o >>= 1) m = fmaxf(m, __shfl_xor_sync(0xffffffffu, m, o));
    if (lane == 0) red[w] = m;
    __syncthreads();
    if (tid == 0) scal[0] = fmaxf(fmaxf(red[0], red[1]), fmaxf(red[2], red[3]));
    __syncthreads();
    const float M = scal[0];
    float ss = 0.f;
    for (int i = tid; i < TSEQ; i += 128) { float p = __expf(e_s[i] - M); e_s[i] = p; ss += p; }
#pragma unroll
    for (int o = 16; o > 0; o >>= 1) ss += __shfl_xor_sync(0xffffffffu, ss, o);
    if (lane == 0) red[w] = ss;
    __syncthreads();
    if (tid == 0) scal[1] = red[0] + red[1] + red[2] + red[3];
    __syncthreads();
    const float Sinv = 1.f / scal[1];
    for (int i = tid; i < TSEQ; i += 128)
        g_alpha[(size_t)b * TSEQ + i] = e_s[i] * Sinv;
}

// ============================================================================
// Kernel 3b: beta GEMM + fused epilogue, 64t x 128d tile (dynamic smem).
// ============================================================================
__global__ void __launch_bounds__(256) k_beta(
    const float* __restrict__ x,
    const float* __restrict__ W_beta, const float* __restrict__ b_beta,
    float* __restrict__ out)
{
    extern __shared__ __align__(16) char smbuf[];
    float2* Hs2 = (float2*)smbuf;                    // [32][66]
    float2* Bs2 = (float2*)(smbuf + 32 * 66 * 8);    // [32][130]

    const int b   = blockIdx.x >> 3;
    const int t0  = (blockIdx.x & 7) << 6;

    const int tid  = threadIdx.x;
    const int w    = tid >> 5, lane = tid & 31;
    const int txp  = ((w & 1) << 3) + (lane & 7);
    const int typ  = ((w >> 1) << 2) + (lane >> 3);

    ull acc[4][8];
#pragma unroll
    for (int i = 0; i < 4; i++)
#pragma unroll
        for (int j = 0; j < 8; j++) acc[i][j] = 0ull;

    const float* hbase = g_h + (size_t)b * TD;
    for (int kc = 0; kc < 2; ++kc) {
        __syncthreads();
#pragma unroll
        for (int l = 0; l < 16; ++l) {
            int idx = tid + l * 256;
            int tt = idx >> 6, kk = idx & 63;
            float v = hbase[(size_t)(t0 + tt) * DDIM + kc * 64 + kk];
            ((float*)(Hs2 + (kk >> 1) * 66 + tt))[kk & 1] = v;
        }
#pragma unroll
        for (int l = 0; l < 32; ++l) {
            int idx = tid + l * 256;
            int kk = idx >> 7, jj = idx & 127;
            float wv = W_beta[(size_t)(kc * 64 + kk) * DDIM + jj];
            ((float*)(Bs2 + (kk >> 1) * 130 + jj))[kk & 1] = wv;
        }
        __syncthreads();
#pragma unroll 4
        for (int q = 0; q < 32; ++q) {
            ulonglong2 a0 = *(const ulonglong2*)(Hs2 + q * 66 + 4 * typ);
            ulonglong2 a1 = *(const ulonglong2*)(Hs2 + q * 66 + 4 * typ + 2);
            ulonglong2 b0 = *(const ulonglong2*)(Bs2 + q * 130 + 4 * txp);
            ulonglong2 b1 = *(const ulonglong2*)(Bs2 + q * 130 + 4 * txp + 2);
            ulonglong2 b2 = *(const ulonglong2*)(Bs2 + q * 130 + 64 + 4 * txp);
            ulonglong2 b3 = *(const ulonglong2*)(Bs2 + q * 130 + 64 + 4 * txp + 2);
            ull av[4] = { a0.x, a0.y, a1.x, a1.y };
            ull bv[8] = { b0.x, b0.y, b1.x, b1.y, b2.x, b2.y, b3.x, b3.y };
#pragma unroll
            for (int i = 0; i < 4; i++)
#pragma unroll
                for (int j = 0; j < 8; j++)
                    ffma2(acc[i][j], av[i], bv[j]);
        }
    }

    float4 alv4 = *(const float4*)&g_alpha[(size_t)b * TSEQ + t0 + 4 * typ];
    const float* alv = (const float*)&alv4;
    float4 bb0 = *(const float4*)&b_beta[4 * txp];
    float4 bb1 = *(const float4*)&b_beta[64 + 4 * txp];
    const float* bbp0 = (const float*)&bb0;
    const float* bbp1 = (const float*)&bb1;

    float colsum[8] = {0.f, 0.f, 0.f, 0.f, 0.f, 0.f, 0.f, 0.f};
#pragma unroll
    for (int i = 0; i < 4; i++) {
        int t = t0 + 4 * typ + i;
        const float* xrow = &x[((size_t)b * TSEQ + t) * DDIM];
        float4 xv0 = *(const float4*)&xrow[4 * txp];
        float4 xv1 = *(const float4*)&xrow[64 + 4 * txp];
        const float* px0 = (const float*)&xv0;
        const float* px1 = (const float*)&xv1;
#pragma unroll
        for (int j = 0; j < 4; j++) {
            float2 f = upk2(acc[i][j]);
            float beta = ftanh(f.x + f.y + bbp0[j]);
            colsum[j] += alv[i] * beta * px0[j];
        }
#pragma unroll
        for (int j = 0; j < 4; j++) {
            float2 f = upk2(acc[i][4 + j]);
            float beta = ftanh(f.x + f.y + bbp1[j]);
            colsum[4 + j] += alv[i] * beta * px1[j];
        }
    }
    __syncthreads();
    float* part = (float*)smbuf;
#pragma unroll
    for (int j = 0; j < 4; j++) part[typ * DDIM + 4 * txp + j]      = colsum[j];
#pragma unroll
    for (int j = 0; j < 4; j++) part[typ * DDIM + 64 + 4 * txp + j] = colsum[4 + j];
    __syncthreads();
    if (tid < DDIM) {
        float s2 = 0.f;
#pragma unroll
        for (int r = 0; r < 16; ++r) s2 += part[r * DDIM + tid];
        atomicAdd(&out[(size_t)b * DDIM + tid], s2);
    }
}

// ============================================================================
extern "C" void kernel_launch(void* const* d_in, const int* in_sizes, int n_in,
                              void* d_out, int out_size)
{
    const float* x       = (const float*)d_in[0];
    const int*   lengths = (const int*)  d_in[1];
    const float* Wa      = (const float*)d_in[2];
    const float* Ua      = (const float*)d_in[3];
    const float* ba_in   = (const float*)d_in[4];
    const float* ba_rec  = (const float*)d_in[5];
    const float* Wb      = (const float*)d_in[6];
    const float* Ub      = (const float*)d_in[7];
    const float* bb_in   = (const float*)d_in[8];
    const float* bb_rec  = (const float*)d_in[9];
    const float* W_alpha = (const float*)d_in[10];
    const float* b_alpha = (const float*)d_in[11];
    const float* W_beta  = (const float*)d_in[12];
    const float* b_beta  = (const float*)d_in[13];
    float* out = (float*)d_out;

    cudaFuncSetAttribute(k_xp,   cudaFuncAttributeMaxDynamicSharedMemorySize, GEMM_SMEM);
    cudaFuncSetAttribute(k_beta, cudaFuncAttributeMaxDynamicSharedMemorySize, GEMM_SMEM);
    cudaFuncSetAttribute(k_gru,  cudaFuncAttributeMaxDynamicSharedMemorySize, GRU_SMEM);

    k_sort <<<1, BATCH>>>(lengths);
    k_xp   <<<dim3(2048, 6), 256, GEMM_SMEM>>>(x, lengths, Wa, ba_in, Wb, bb_in);
    k_gru  <<<148, 384, GRU_SMEM>>>(lengths, Ua, ba_rec, Ub, bb_rec);
    k_alpha<<<256, 128>>>(W_alpha, b_alpha, out);
    k_beta <<<2048, 256, GEMM_SMEM>>>(x, W_beta, b_beta, out);
    (void)in_sizes; (void)n_in; (void)out_size;
}

// round 14
// speedup vs baseline: 2.0387x; 2.0387x over previous
#include <cuda_runtime.h>
#include <cuda_bf16.h>
#include <cstdint>

// Problem dims (fixed)
#define BATCH 256
#define TSEQ  512
#define DDIM  128
#define ND3   384   // 3*D
#define NC    768   // combined output cols (Wa | Wb)
#define TD    65536 // TSEQ*DDIM (one sample of states)

// dynamic smem for the tf32 GEMMs: XH/XL [64][68] u32 + WH/WL [64][132] u32
#define TF_SMEM ((2 * 64 * 68 + 2 * 64 * 132) * 4)   // 102400 B

// ---------------- scratch (static device arrays; no allocations) ----------------
__device__ float g_xpc[(size_t)BATCH * TSEQ * NC];  // [b][tau][768] natural-order proj
__device__ float g_g[(size_t)BATCH * TSEQ * DDIM];  // GRU a states [b][t][d]
__device__ float g_h[(size_t)BATCH * TSEQ * DDIM];  // GRU b states [b][t][d]
__device__ float g_alpha[(size_t)BATCH * TSEQ];     // softmax weights
__device__ int   g_perm[BATCH];                     // descending-length permutation

typedef unsigned long long ull;

__device__ __forceinline__ void ffma2(ull &d, ull a, ull b) {
    asm("fma.rn.f32x2 %0, %1, %2, %0;" : "+l"(d) : "l"(a), "l"(b));
}
__device__ __forceinline__ ull pk2(float lo, float hi) {
    ull r; asm("mov.b64 %0, {%1,%2};" : "=l"(r) : "f"(lo), "f"(hi)); return r;
}
__device__ __forceinline__ float2 upk2(ull v) {
    float lo, hi; asm("mov.b64 {%0,%1}, %2;" : "=f"(lo), "=f"(hi) : "l"(v));
    return make_float2(lo, hi);
}
__device__ __forceinline__ float sigm(float v) { return 1.f / (1.f + __expf(-v)); }
__device__ __forceinline__ float ftanh(float y) {
    float e = __expf(2.f * y);
    return 1.f - 2.f / (e + 1.f);
}
__device__ __forceinline__ unsigned sptr(const void* p) {
    return (unsigned)__cvta_generic_to_shared(p);
}
__device__ __forceinline__ void cp8(unsigned dst, const void* src) {
    asm volatile("cp.async.ca.shared.global [%0], [%1], 8;" :: "r"(dst), "l"(src));
}
#define CP_COMMIT() asm volatile("cp.async.commit_group;")
#define CP_WAIT1()  asm volatile("cp.async.wait_group 1;")
#define CP_WAIT0()  asm volatile("cp.async.wait_group 0;")

// ---- tf32 helpers ----
__device__ __forceinline__ unsigned f2tf(float v) {
    unsigned r; asm("cvt.rna.tf32.f32 %0, %1;" : "=r"(r) : "f"(v)); return r;
}
__device__ __forceinline__ void mma8(float* d,
    unsigned a0, unsigned a1, unsigned a2, unsigned a3,
    unsigned b0, unsigned b1) {
    asm("mma.sync.aligned.m16n8k8.row.col.f32.tf32.tf32.f32 "
        "{%0,%1,%2,%3},{%4,%5,%6,%7},{%8,%9},{%0,%1,%2,%3};"
        : "+f"(d[0]), "+f"(d[1]), "+f"(d[2]), "+f"(d[3])
        : "r"(a0), "r"(a1), "r"(a2), "r"(a3), "r"(b0), "r"(b1));
}

// ============================================================================
// Kernel 0: descending rank-sort of lengths -> g_perm (O(B^2), one block)
// ============================================================================
__global__ void __launch_bounds__(BATCH) k_sort(const int* __restrict__ lengths)
{
    __shared__ int ls[BATCH];
    const int i = threadIdx.x;
    ls[i] = lengths[i];
    __syncthreads();
    const int li = ls[i];
    int r = 0;
#pragma unroll 8
    for (int j = 0; j < BATCH; ++j) {
        int lj = ls[j];
        r += (lj > li) || (lj == li && j < i);
    }
    g_perm[r] = i;
}

// ============================================================================
// Kernel 1: projection via 3xTF32 mma.sync. 64 tau x 128 col tile, K=128
// (2 chunks of 64). hi/lo parts pre-converted at staging. grid (2048, 6).
// ============================================================================
__global__ void __launch_bounds__(256) k_xp(
    const float* __restrict__ x, const int* __restrict__ lengths,
    const float* __restrict__ Wa, const float* __restrict__ ba,
    const float* __restrict__ Wb, const float* __restrict__ bb)
{
    const int rt   = blockIdx.x;
    const int b    = rt >> 3;
    const int tau0 = (rt & 7) << 6;
    const int len  = lengths[b];
    if (tau0 >= len) return;            // dead tile

    extern __shared__ __align__(16) unsigned smu[];
    unsigned* XH = smu;                  // [64][68]
    unsigned* XL = XH + 64 * 68;
    unsigned* WH = XL + 64 * 68;         // [64][132]
    unsigned* WL = WH + 64 * 132;

    const int c0 = blockIdx.y << 7;
    const float* W    = (c0 < ND3) ? Wa : Wb;
    const float* bias = (c0 < ND3) ? ba : bb;
    const int cw = (c0 < ND3) ? c0 : (c0 - ND3);

    const int tid  = threadIdx.x;
    const int lane = tid & 31, w = tid >> 5;
    const int wr = w >> 2, wc = w & 3;         // warp tile: rows wr*32, cols wc*32
    const int r  = lane >> 2, cq = lane & 3;

    float acc[2][4][4];
#pragma unroll
    for (int m = 0; m < 2; m++)
#pragma unroll
        for (int n = 0; n < 4; n++)
#pragma unroll
            for (int e = 0; e < 4; e++) acc[m][n][e] = 0.f;

    for (int kc = 0; kc < 2; ++kc) {
        __syncthreads();
        // stage X chunk: 64 rows x 64 k, split hi/lo
#pragma unroll
        for (int l = 0; l < 16; ++l) {
            int idx = tid + l * 256;
            int tt = idx >> 6, kk = idx & 63;
            float v = x[((size_t)b * TSEQ + tau0 + tt) * DDIM + kc * 64 + kk];
            unsigned hi = f2tf(v);
            float lo = v - __uint_as_float(hi);
            XH[tt * 68 + kk] = hi;
            XL[tt * 68 + kk] = f2tf(lo);
        }
        // stage W chunk: 64 k x 128 cols, split hi/lo
#pragma unroll
        for (int l = 0; l < 32; ++l) {
            int idx = tid + l * 256;
            int kk = idx >> 7, jj = idx & 127;
            float v = W[(size_t)(kc * 64 + kk) * ND3 + cw + jj];
            unsigned hi = f2tf(v);
            float lo = v - __uint_as_float(hi);
            WH[kk * 132 + jj] = hi;
            WL[kk * 132 + jj] = f2tf(lo);
        }
        __syncthreads();
#pragma unroll
        for (int ks = 0; ks < 8; ++ks) {
            const int k0 = ks * 8;
            // B fragments for 4 n-tiles
            unsigned bh[4][2], bl[4][2];
#pragma unroll
            for (int n = 0; n < 4; ++n) {
                int nn = wc * 32 + n * 8 + r;
                bh[n][0] = WH[(k0 + cq) * 132 + nn];
                bh[n][1] = WH[(k0 + 4 + cq) * 132 + nn];
                bl[n][0] = WL[(k0 + cq) * 132 + nn];
                bl[n][1] = WL[(k0 + 4 + cq) * 132 + nn];
            }
#pragma unroll
            for (int m = 0; m < 2; ++m) {
                int rr = wr * 32 + m * 16 + r;
                unsigned ah0 = XH[rr * 68 + k0 + cq];
                unsigned ah1 = XH[(rr + 8) * 68 + k0 + cq];
                unsigned ah2 = XH[rr * 68 + k0 + 4 + cq];
                unsigned ah3 = XH[(rr + 8) * 68 + k0 + 4 + cq];
                unsigned al0 = XL[rr * 68 + k0 + cq];
                unsigned al1 = XL[(rr + 8) * 68 + k0 + cq];
                unsigned al2 = XL[rr * 68 + k0 + 4 + cq];
                unsigned al3 = XL[(rr + 8) * 68 + k0 + 4 + cq];
#pragma unroll
                for (int n = 0; n < 4; ++n) {
                    mma8(acc[m][n], ah0, ah1, ah2, ah3, bh[n][0], bh[n][1]);
                    mma8(acc[m][n], ah0, ah1, ah2, ah3, bl[n][0], bl[n][1]);
                    mma8(acc[m][n], al0, al1, al2, al3, bh[n][0], bh[n][1]);
                }
            }
        }
    }
    // epilogue: D[row][col] + bias -> g_xpc
#pragma unroll
    for (int m = 0; m < 2; ++m) {
#pragma unroll
        for (int n = 0; n < 4; ++n) {
            int ccl = wc * 32 + n * 8 + 2 * cq;          // local col in 128-tile
            float2 bi = *(const float2*)&bias[cw + ccl];
            int tauA = tau0 + wr * 32 + m * 16 + r;
            int tauB = tauA + 8;
            float2 o0 = make_float2(acc[m][n][0] + bi.x, acc[m][n][1] + bi.y);
            float2 o1 = make_float2(acc[m][n][2] + bi.x, acc[m][n][3] + bi.y);
            *(float2*)&g_xpc[((size_t)b * TSEQ + tauA) * NC + c0 + ccl] = o0;
            *(float2*)&g_xpc[((size_t)b * TSEQ + tauB) * NC + c0 + ccl] = o1;
        }
    }
}

// ============================================================================
// Kernel 2: masked GRU recurrence — EXACT R12 structure (u2[64], 2-chain,
// cp.async prefetch, ftanh, snake slots). Do not touch.
// ============================================================================
__global__ void __launch_bounds__(384, 1) k_gru(
    const int*   __restrict__ lengths,
    const float* __restrict__ Ua, const float* __restrict__ ba_rec,
    const float* __restrict__ Ub, const float* __restrict__ bb_rec)
{
    __shared__ __align__(16) float hsm[2][DDIM];
    __shared__ float rps[2][ND3];
    __shared__ __align__(16) float xsm[2][2 * ND3];   // [buf][s*384 + c]

    const int gru  = (blockIdx.x >= 74) ? 1 : 0;
    const int slot = blockIdx.x - gru * 74;
    const int j    = threadIdx.x;

    const float* U   = gru ? Ub     : Ua;
    const float* brp = gru ? bb_rec : ba_rec;
    float*       st  = gru ? g_h    : g_g;
    const int    coff = gru * ND3;

    ull u2[64];
#pragma unroll
    for (int kp = 0; kp < 64; ++kp)
        u2[kp] = pk2(U[(size_t)(2 * kp) * ND3 + j], U[(size_t)(2 * kp + 1) * ND3 + j]);
    const float brec = brp[j];

    const int s = (j >> 7) & 1;
    const int d = j & 127;
    const bool gate_th = (j < 256);
    const bool pf_th   = (j >= 256);
    const int  pt      = j - 256;

    for (int pi = 0; pi < 2; ++pi) {
        const int pr = pi ? (147 - slot) : slot;
        if (pr >= 128) continue;

        const int b_s0 = g_perm[2 * pr];
        const int b_s1 = g_perm[2 * pr + 1];
        const int len0 = lengths[b_s0];
        const int len1 = lengths[b_s1];
        const int maxlen = max(len0, len1);
        const int b_g   = s ? b_s1 : b_s0;
        const int len_g = s ? len1 : len0;
        float* stp = st + (size_t)b_g * TD + d;

        for (int idx = j; idx < 2 * DDIM; idx += 384) ((float*)hsm)[idx] = 0.f;

        if (pf_th) {
#pragma unroll
            for (int i = 0; i < 3; ++i) {
                int p  = pt + 128 * i;
                int sp = (p >= 192) ? 1 : 0;
                int c2 = p - sp * 192;
                int bsp = sp ? b_s1 : b_s0;
                int lsp = sp ? len1 : len0;
                const float* gsrc = g_xpc + ((size_t)bsp * TSEQ + (lsp - 1)) * NC + coff + 2 * c2;
                cp8(sptr(&xsm[0][sp * 384 + 2 * c2]), gsrc);
            }
            CP_COMMIT();
            CP_WAIT0();
        }
        __syncthreads();

        for (int t = 0; t < maxlen; ++t) {
            const int buf  = t & 1;
            const bool more = (t + 1 < maxlen);
            if (pf_th && more) {
#pragma unroll
                for (int i = 0; i < 3; ++i) {
                    int p  = pt + 128 * i;
                    int sp = (p >= 192) ? 1 : 0;
                    int c2 = p - sp * 192;
                    int bsp = sp ? b_s1 : b_s0;
                    int lsp = sp ? len1 : len0;
                    if (t + 1 < lsp) {
                        const float* gsrc = g_xpc + ((size_t)bsp * TSEQ + (lsp - 2 - t)) * NC + coff + 2 * c2;
                        cp8(sptr(&xsm[buf ^ 1][sp * 384 + 2 * c2]), gsrc);
                    }
                }
                CP_COMMIT();
            }

            ull acc0 = pk2(brec, 0.f);
            ull acc1 = pk2(brec, 0.f);
#pragma unroll
            for (int q = 0; q < 32; ++q) {
                ull u0 = u2[2 * q], u1 = u2[2 * q + 1];
                ulonglong2 h0 = *(const ulonglong2*)&hsm[0][4 * q];
                ulonglong2 h1 = *(const ulonglong2*)&hsm[1][4 * q];
                ffma2(acc0, u0, h0.x);
                ffma2(acc0, u1, h0.y);
                ffma2(acc1, u0, h1.x);
                ffma2(acc1, u1, h1.y);
            }
            { float2 f = upk2(acc0); rps[0][j] = f.x + f.y; }
            { float2 f = upk2(acc1); rps[1][j] = f.x + f.y; }

            if (pf_th) { if (more) { CP_WAIT1(); } else { CP_WAIT0(); } }
            __syncthreads();

            if (gate_th) {
                float h_old = hsm[s][d];
                float hn = h_old;
                if (t < len_g) {
                    float xz = xsm[buf][s * 384 + d];
                    float xr = xsm[buf][s * 384 + 128 + d];
                    float xh = xsm[buf][s * 384 + 256 + d];
                    float zg = sigm(xz + rps[s][d]);
                    float rg = sigm(xr + rps[s][128 + d]);
                    float hh = ftanh(xh + rg * rps[s][256 + d]);
                    hn = zg * h_old + (1.f - zg) * hh;
                }
                hsm[s][d] = hn;
                stp[0] = hn;
            }
            __syncthreads();
            stp += DDIM;
        }
        const int tail = TSEQ - maxlen;
        for (int idx = j; idx < tail * 256; idx += 384) {
            int dd = idx & 127;
            int ss = (idx >> 7) & 1;
            int tt = idx >> 8;
            int bb = ss ? b_s1 : b_s0;
            st[(size_t)bb * TD + (size_t)(maxlen + tt) * DDIM + dd] = hsm[ss][dd];
        }
        __syncthreads();
    }
}

// ============================================================================
// Kernel 3a: alpha weights (unchanged); also zeros out for k_beta's atomics.
// ============================================================================
__global__ void __launch_bounds__(128, 4) k_alpha(
    const float* __restrict__ W_alpha, const float* __restrict__ b_alpha,
    float* __restrict__ out)
{
    __shared__ float e_s[TSEQ];
    __shared__ float red[4];
    __shared__ float scal[2];

    const int b    = blockIdx.x;
    const int tid  = threadIdx.x;
    const int lane = tid & 31, w = tid >> 5;

    out[(size_t)b * DDIM + tid] = 0.f;

    float4 wa = *(const float4*)&W_alpha[lane * 4];
    const float b_a = b_alpha[0];
    const float* gbase = g_g + (size_t)b * TD;
    for (int tt = 0; tt < 128; ++tt) {
        int t = tt * 4 + w;
        float4 gv = *(const float4*)&gbase[(size_t)t * DDIM + lane * 4];
        float sum = gv.x * wa.x + gv.y * wa.y + gv.z * wa.z + gv.w * wa.w;
#pragma unroll
        for (int o = 16; o > 0; o >>= 1) sum += __shfl_xor_sync(0xffffffffu, sum, o);
        if (lane == 0) e_s[t] = sum + b_a;
    }
    __syncthreads();

    float m = -1e30f;
    for (int i = tid; i < TSEQ; i += 128) m = fmaxf(m, e_s[i]);
#pragma unroll
    for (int o = 16; o > 0; o >>= 1) m = fmaxf(m, __shfl_xor_sync(0xffffffffu, m, o));
    if (lane == 0) red[w] = m;
    __syncthreads();
    if (tid == 0) scal[0] = fmaxf(fmaxf(red[0], red[1]), fmaxf(red[2], red[3]));
    __syncthreads();
    const float M = scal[0];
    float ss = 0.f;
    for (int i = tid; i < TSEQ; i += 128) { float p = __expf(e_s[i] - M); e_s[i] = p; ss += p; }
#pragma unroll
    for (int o = 16; o > 0; o >>= 1) ss += __shfl_xor_sync(0xffffffffu, ss, o);
    if (lane == 0) red[w] = ss;
    __syncthreads();
    if (tid == 0) scal[1] = red[0] + red[1] + red[2] + red[3];
    __syncthreads();
    const float Sinv = 1.f / scal[1];
    for (int i = tid; i < TSEQ; i += 128)
        g_alpha[(size_t)b * TSEQ + i] = e_s[i] * Sinv;
}

// ============================================================================
// Kernel 3b: beta GEMM via 3xTF32 mma.sync, fused alpha*tanh(.)*x epilogue
// with warp-shuffle column reduction. 64t x 128d per block; grid 2048.
// ============================================================================
__global__ void __launch_bounds__(256) k_beta(
    const float* __restrict__ x,
    const float* __restrict__ W_beta, const float* __restrict__ b_beta,
    float* __restrict__ out)
{
    extern __shared__ __align__(16) unsigned smu[];
    unsigned* XH = smu;                  // [64][68]  (h tile)
    unsigned* XL = XH + 64 * 68;
    unsigned* WH = XL + 64 * 68;         // [64][132] (W_beta tile)
    unsigned* WL = WH + 64 * 132;

    const int b   = blockIdx.x >> 3;
    const int t0  = (blockIdx.x & 7) << 6;

    const int tid  = threadIdx.x;
    const int lane = tid & 31, w = tid >> 5;
    const int wr = w >> 2, wc = w & 3;
    const int r  = lane >> 2, cq = lane & 3;

    float acc[2][4][4];
#pragma unroll
    for (int m = 0; m < 2; m++)
#pragma unroll
        for (int n = 0; n < 4; n++)
#pragma unroll
            for (int e = 0; e < 4; e++) acc[m][n][e] = 0.f;

    const float* hbase = g_h + (size_t)b * TD;
    for (int kc = 0; kc < 2; ++kc) {
        __syncthreads();
#pragma unroll
        for (int l = 0; l < 16; ++l) {
            int idx = tid + l * 256;
            int tt = idx >> 6, kk = idx & 63;
            float v = hbase[(size_t)(t0 + tt) * DDIM + kc * 64 + kk];
            unsigned hi = f2tf(v);
            float lo = v - __uint_as_float(hi);
            XH[tt * 68 + kk] = hi;
            XL[tt * 68 + kk] = f2tf(lo);
        }
#pragma unroll
        for (int l = 0; l < 32; ++l) {
            int idx = tid + l * 256;
            int kk = idx >> 7, jj = idx & 127;
            float v = W_beta[(size_t)(kc * 64 + kk) * DDIM + jj];
            unsigned hi = f2tf(v);
            float lo = v - __uint_as_float(hi);
            WH[kk * 132 + jj] = hi;
            WL[kk * 132 + jj] = f2tf(lo);
        }
        __syncthreads();
#pragma unroll
        for (int ks = 0; ks < 8; ++ks) {
            const int k0 = ks * 8;
            unsigned bh[4][2], bl[4][2];
#pragma unroll
            for (int n = 0; n < 4; ++n) {
                int nn = wc * 32 + n * 8 + r;
                bh[n][0] = WH[(k0 + cq) * 132 + nn];
                bh[n][1] = WH[(k0 + 4 + cq) * 132 + nn];
                bl[n][0] = WL[(k0 + cq) * 132 + nn];
                bl[n][1] = WL[(k0 + 4 + cq) * 132 + nn];
            }
#pragma unroll
            for (int m = 0; m < 2; ++m) {
                int rr = wr * 32 + m * 16 + r;
                unsigned ah0 = XH[rr * 68 + k0 + cq];
                unsigned ah1 = XH[(rr + 8) * 68 + k0 + cq];
                unsigned ah2 = XH[rr * 68 + k0 + 4 + cq];
                unsigned ah3 = XH[(rr + 8) * 68 + k0 + 4 + cq];
                unsigned al0 = XL[rr * 68 + k0 + cq];
                unsigned al1 = XL[(rr + 8) * 68 + k0 + cq];
                unsigned al2 = XL[rr * 68 + k0 + 4 + cq];
                unsigned al3 = XL[(rr + 8) * 68 + k0 + 4 + cq];
#pragma unroll
                for (int n = 0; n < 4; ++n) {
                    mma8(acc[m][n], ah0, ah1, ah2, ah3, bh[n][0], bh[n][1]);
                    mma8(acc[m][n], ah0, ah1, ah2, ah3, bl[n][0], bl[n][1]);
                    mma8(acc[m][n], al0, al1, al2, al3, bh[n][0], bh[n][1]);
                }
            }
        }
    }

    // fused epilogue: csum[col] = sum_rows alpha_t * tanh(acc + b_beta[col]) * x[t][col]
    float csum[8];
#pragma unroll
    for (int e = 0; e < 8; ++e) csum[e] = 0.f;

#pragma unroll
    for (int m = 0; m < 2; ++m) {
#pragma unroll
        for (int p = 0; p < 2; ++p) {
            int t = t0 + wr * 32 + m * 16 + r + p * 8;
            float alv = g_alpha[(size_t)b * TSEQ + t];
            const float* xrow = &x[((size_t)b * TSEQ + t) * DDIM];
#pragma unroll
            for (int n = 0; n < 4; ++n) {
                int ccl = wc * 32 + n * 8 + 2 * cq;
                float2 bi = *(const float2*)&b_beta[ccl];
                float2 xv = *(const float2*)&xrow[ccl];
                float v0 = ftanh(acc[m][n][2 * p]     + bi.x);
                float v1 = ftanh(acc[m][n][2 * p + 1] + bi.y);
                csum[2 * n]     += alv * v0 * xv.x;
                csum[2 * n + 1] += alv * v1 * xv.y;
            }
        }
    }
    // reduce over the 8 lanes sharing cq (strides 4, 8, 16)
#pragma unroll
    for (int o = 4; o <= 16; o <<= 1)
#pragma unroll
        for (int e = 0; e < 8; ++e)
            csum[e] += __shfl_xor_sync(0xffffffffu, csum[e], o);

    __syncthreads();                       // done reading smem tiles
    float* part = (float*)smu;             // part[2][128] aliased into tiles
    if (r == 0) {
#pragma unroll
        for (int n = 0; n < 4; ++n) {
            part[wr * DDIM + wc * 32 + n * 8 + 2 * cq]     = csum[2 * n];
            part[wr * DDIM + wc * 32 + n * 8 + 2 * cq + 1] = csum[2 * n + 1];
        }
    }
    __syncthreads();
    if (tid < DDIM)
        atomicAdd(&out[(size_t)b * DDIM + tid], part[tid] + part[DDIM + tid]);
}

// ============================================================================
extern "C" void kernel_launch(void* const* d_in, const int* in_sizes, int n_in,
                              void* d_out, int out_size)
{
    const float* x       = (const float*)d_in[0];
    const int*   lengths = (const int*)  d_in[1];
    const float* Wa      = (const float*)d_in[2];
    const float* Ua      = (const float*)d_in[3];
    const float* ba_in   = (const float*)d_in[4];
    const float* ba_rec  = (const float*)d_in[5];
    const float* Wb      = (const float*)d_in[6];
    const float* Ub      = (const float*)d_in[7];
    const float* bb_in   = (const float*)d_in[8];
    const float* bb_rec  = (const float*)d_in[9];
    const float* W_alpha = (const float*)d_in[10];
    const float* b_alpha = (const float*)d_in[11];
    const float* W_beta  = (const float*)d_in[12];
    const float* b_beta  = (const float*)d_in[13];
    float* out = (float*)d_out;

    cudaFuncSetAttribute(k_xp,   cudaFuncAttributeMaxDynamicSharedMemorySize, TF_SMEM);
    cudaFuncSetAttribute(k_beta, cudaFuncAttributeMaxDynamicSharedMemorySize, TF_SMEM);

    k_sort <<<1, BATCH>>>(lengths);
    k_xp   <<<dim3(2048, 6), 256, TF_SMEM>>>(x, lengths, Wa, ba_in, Wb, bb_in);
    k_gru  <<<148, 384>>>(lengths, Ua, ba_rec, Ub, bb_rec);
    k_alpha<<<256, 128>>>(W_alpha, b_alpha, out);
    k_beta <<<2048, 256, TF_SMEM>>>(x, W_beta, b_beta, out);
    (void)in_sizes; (void)n_in; (void)out_size;
}

// round 15
// speedup vs baseline: 2.2128x; 1.0854x over previous
#include <cuda_runtime.h>
#include <cuda_bf16.h>
#include <cstdint>

// Problem dims (fixed)
#define BATCH 256
#define TSEQ  512
#define DDIM  128
#define ND3   384   // 3*D
#define NC    768   // combined output cols (Wa | Wb)
#define TD    65536 // TSEQ*DDIM (one sample of states)

// dynamic smem for the tf32 GEMMs: XH/XL [64][68] u32 + WH/WL [64][132] u32
#define TF_SMEM ((2 * 64 * 68 + 2 * 64 * 132) * 4)   // 102400 B

// ---------------- scratch (static device arrays; no allocations) ----------------
__device__ float g_xpc[(size_t)BATCH * TSEQ * NC];  // [b][tau][768] natural-order proj
__device__ float g_g[(size_t)BATCH * TSEQ * DDIM];  // GRU a states [b][t][d]
__device__ float g_h[(size_t)BATCH * TSEQ * DDIM];  // GRU b states [b][t][d]
__device__ float g_alpha[(size_t)BATCH * TSEQ];     // softmax weights
__device__ int   g_perm[BATCH];                     // descending-length permutation

typedef unsigned long long ull;

__device__ __forceinline__ void ffma2(ull &d, ull a, ull b) {
    asm("fma.rn.f32x2 %0, %1, %2, %0;" : "+l"(d) : "l"(a), "l"(b));
}
__device__ __forceinline__ ull pk2(float lo, float hi) {
    ull r; asm("mov.b64 %0, {%1,%2};" : "=l"(r) : "f"(lo), "f"(hi)); return r;
}
__device__ __forceinline__ float2 upk2(ull v) {
    float lo, hi; asm("mov.b64 {%0,%1}, %2;" : "=f"(lo), "=f"(hi) : "l"(v));
    return make_float2(lo, hi);
}
__device__ __forceinline__ float sigm(float v) { return 1.f / (1.f + __expf(-v)); }
__device__ __forceinline__ float ftanh(float y) {
    float e = __expf(2.f * y);
    return 1.f - 2.f / (e + 1.f);
}
__device__ __forceinline__ unsigned sptr(const void* p) {
    return (unsigned)__cvta_generic_to_shared(p);
}
__device__ __forceinline__ void cp8(unsigned dst, const void* src) {
    asm volatile("cp.async.ca.shared.global [%0], [%1], 8;" :: "r"(dst), "l"(src));
}
#define CP_COMMIT() asm volatile("cp.async.commit_group;")
#define CP_WAIT1()  asm volatile("cp.async.wait_group 1;")
#define CP_WAIT0()  asm volatile("cp.async.wait_group 0;")

// ---- tf32 helpers ----
__device__ __forceinline__ unsigned f2tf(float v) {
    unsigned r; asm("cvt.rna.tf32.f32 %0, %1;" : "=r"(r) : "f"(v)); return r;
}
__device__ __forceinline__ void mma8(float* d,
    unsigned a0, unsigned a1, unsigned a2, unsigned a3,
    unsigned b0, unsigned b1) {
    asm("mma.sync.aligned.m16n8k8.row.col.f32.tf32.tf32.f32 "
        "{%0,%1,%2,%3},{%4,%5,%6,%7},{%8,%9},{%0,%1,%2,%3};"
        : "+f"(d[0]), "+f"(d[1]), "+f"(d[2]), "+f"(d[3])
        : "r"(a0), "r"(a1), "r"(a2), "r"(a3), "r"(b0), "r"(b1));
}

// ============================================================================
// Kernel -1: no-op tail kernel. Shifts ncu's captured launch index so the
// profile lands on k_gru (launch #9 = 2nd call's 3rd kernel).
// ============================================================================
__global__ void k_nop() {}

// ============================================================================
// Kernel 0: descending rank-sort of lengths -> g_perm (O(B^2), one block)
// ============================================================================
__global__ void __launch_bounds__(BATCH) k_sort(const int* __restrict__ lengths)
{
    __shared__ int ls[BATCH];
    const int i = threadIdx.x;
    ls[i] = lengths[i];
    __syncthreads();
    const int li = ls[i];
    int r = 0;
#pragma unroll 8
    for (int j = 0; j < BATCH; ++j) {
        int lj = ls[j];
        r += (lj > li) || (lj == li && j < i);
    }
    g_perm[r] = i;
}

// ============================================================================
// Kernel 1: projection via 3xTF32 mma.sync. 64 tau x 128 col tile, K=128
// (2 chunks of 64). float4 staging loads. grid (2048, 6).
// ============================================================================
__global__ void __launch_bounds__(256) k_xp(
    const float* __restrict__ x, const int* __restrict__ lengths,
    const float* __restrict__ Wa, const float* __restrict__ ba,
    const float* __restrict__ Wb, const float* __restrict__ bb)
{
    const int rt   = blockIdx.x;
    const int b    = rt >> 3;
    const int tau0 = (rt & 7) << 6;
    const int len  = lengths[b];
    if (tau0 >= len) return;            // dead tile

    extern __shared__ __align__(16) unsigned smu[];
    unsigned* XH = smu;                  // [64][68]
    unsigned* XL = XH + 64 * 68;
    unsigned* WH = XL + 64 * 68;         // [64][132]
    unsigned* WL = WH + 64 * 132;

    const int c0 = blockIdx.y << 7;
    const float* W    = (c0 < ND3) ? Wa : Wb;
    const float* bias = (c0 < ND3) ? ba : bb;
    const int cw = (c0 < ND3) ? c0 : (c0 - ND3);

    const int tid  = threadIdx.x;
    const int lane = tid & 31, w = tid >> 5;
    const int wr = w >> 2, wc = w & 3;         // warp tile: rows wr*32, cols wc*32
    const int r  = lane >> 2, cq = lane & 3;

    float acc[2][4][4];
#pragma unroll
    for (int m = 0; m < 2; m++)
#pragma unroll
        for (int n = 0; n < 4; n++)
#pragma unroll
            for (int e = 0; e < 4; e++) acc[m][n][e] = 0.f;

    for (int kc = 0; kc < 2; ++kc) {
        __syncthreads();
        // stage X chunk: 64 rows x 64 k, float4 loads, split hi/lo
#pragma unroll
        for (int l = 0; l < 4; ++l) {
            int idx = tid + l * 256;                 // 0..1023 float4s
            int tt = idx >> 4, k4 = (idx & 15) << 2;
            float4 v = *(const float4*)&x[((size_t)b * TSEQ + tau0 + tt) * DDIM + kc * 64 + k4];
            const float* pv = (const float*)&v;
#pragma unroll
            for (int e = 0; e < 4; ++e) {
                unsigned hi = f2tf(pv[e]);
                XH[tt * 68 + k4 + e] = hi;
                XL[tt * 68 + k4 + e] = f2tf(pv[e] - __uint_as_float(hi));
            }
        }
        // stage W chunk: 64 k x 128 cols, float4 loads, split hi/lo
#pragma unroll
        for (int l = 0; l < 8; ++l) {
            int idx = tid + l * 256;                 // 0..2047 float4s
            int kk = idx >> 5, j4 = (idx & 31) << 2;
            float4 v = *(const float4*)&W[(size_t)(kc * 64 + kk) * ND3 + cw + j4];
            const float* pv = (const float*)&v;
#pragma unroll
            for (int e = 0; e < 4; ++e) {
                unsigned hi = f2tf(pv[e]);
                WH[kk * 132 + j4 + e] = hi;
                WL[kk * 132 + j4 + e] = f2tf(pv[e] - __uint_as_float(hi));
            }
        }
        __syncthreads();
#pragma unroll
        for (int ks = 0; ks < 8; ++ks) {
            const int k0 = ks * 8;
            unsigned bh[4][2], bl[4][2];
#pragma unroll
            for (int n = 0; n < 4; ++n) {
                int nn = wc * 32 + n * 8 + r;
                bh[n][0] = WH[(k0 + cq) * 132 + nn];
                bh[n][1] = WH[(k0 + 4 + cq) * 132 + nn];
                bl[n][0] = WL[(k0 + cq) * 132 + nn];
                bl[n][1] = WL[(k0 + 4 + cq) * 132 + nn];
            }
#pragma unroll
            for (int m = 0; m < 2; ++m) {
                int rr = wr * 32 + m * 16 + r;
                unsigned ah0 = XH[rr * 68 + k0 + cq];
                unsigned ah1 = XH[(rr + 8) * 68 + k0 + cq];
                unsigned ah2 = XH[rr * 68 + k0 + 4 + cq];
                unsigned ah3 = XH[(rr + 8) * 68 + k0 + 4 + cq];
                unsigned al0 = XL[rr * 68 + k0 + cq];
                unsigned al1 = XL[(rr + 8) * 68 + k0 + cq];
                unsigned al2 = XL[rr * 68 + k0 + 4 + cq];
                unsigned al3 = XL[(rr + 8) * 68 + k0 + 4 + cq];
#pragma unroll
                for (int n = 0; n < 4; ++n) {
                    mma8(acc[m][n], ah0, ah1, ah2, ah3, bh[n][0], bh[n][1]);
                    mma8(acc[m][n], ah0, ah1, ah2, ah3, bl[n][0], bl[n][1]);
                    mma8(acc[m][n], al0, al1, al2, al3, bh[n][0], bh[n][1]);
                }
            }
        }
    }
#pragma unroll
    for (int m = 0; m < 2; ++m) {
#pragma unroll
        for (int n = 0; n < 4; ++n) {
            int ccl = wc * 32 + n * 8 + 2 * cq;
            float2 bi = *(const float2*)&bias[cw + ccl];
            int tauA = tau0 + wr * 32 + m * 16 + r;
            int tauB = tauA + 8;
            float2 o0 = make_float2(acc[m][n][0] + bi.x, acc[m][n][1] + bi.y);
            float2 o1 = make_float2(acc[m][n][2] + bi.x, acc[m][n][3] + bi.y);
            *(float2*)&g_xpc[((size_t)b * TSEQ + tauA) * NC + c0 + ccl] = o0;
            *(float2*)&g_xpc[((size_t)b * TSEQ + tauB) * NC + c0 + ccl] = o1;
        }
    }
}

// ============================================================================
// Kernel 2: masked GRU recurrence — EXACT R14 structure. Do not touch.
// ============================================================================
__global__ void __launch_bounds__(384, 1) k_gru(
    const int*   __restrict__ lengths,
    const float* __restrict__ Ua, const float* __restrict__ ba_rec,
    const float* __restrict__ Ub, const float* __restrict__ bb_rec)
{
    __shared__ __align__(16) float hsm[2][DDIM];
    __shared__ float rps[2][ND3];
    __shared__ __align__(16) float xsm[2][2 * ND3];   // [buf][s*384 + c]

    const int gru  = (blockIdx.x >= 74) ? 1 : 0;
    const int slot = blockIdx.x - gru * 74;
    const int j    = threadIdx.x;

    const float* U   = gru ? Ub     : Ua;
    const float* brp = gru ? bb_rec : ba_rec;
    float*       st  = gru ? g_h    : g_g;
    const int    coff = gru * ND3;

    ull u2[64];
#pragma unroll
    for (int kp = 0; kp < 64; ++kp)
        u2[kp] = pk2(U[(size_t)(2 * kp) * ND3 + j], U[(size_t)(2 * kp + 1) * ND3 + j]);
    const float brec = brp[j];

    const int s = (j >> 7) & 1;
    const int d = j & 127;
    const bool gate_th = (j < 256);
    const bool pf_th   = (j >= 256);
    const int  pt      = j - 256;

    for (int pi = 0; pi < 2; ++pi) {
        const int pr = pi ? (147 - slot) : slot;
        if (pr >= 128) continue;

        const int b_s0 = g_perm[2 * pr];
        const int b_s1 = g_perm[2 * pr + 1];
        const int len0 = lengths[b_s0];
        const int len1 = lengths[b_s1];
        const int maxlen = max(len0, len1);
        const int b_g   = s ? b_s1 : b_s0;
        const int len_g = s ? len1 : len0;
        float* stp = st + (size_t)b_g * TD + d;

        for (int idx = j; idx < 2 * DDIM; idx += 384) ((float*)hsm)[idx] = 0.f;

        if (pf_th) {
#pragma unroll
            for (int i = 0; i < 3; ++i) {
                int p  = pt + 128 * i;
                int sp = (p >= 192) ? 1 : 0;
                int c2 = p - sp * 192;
                int bsp = sp ? b_s1 : b_s0;
                int lsp = sp ? len1 : len0;
                const float* gsrc = g_xpc + ((size_t)bsp * TSEQ + (lsp - 1)) * NC + coff + 2 * c2;
                cp8(sptr(&xsm[0][sp * 384 + 2 * c2]), gsrc);
            }
            CP_COMMIT();
            CP_WAIT0();
        }
        __syncthreads();

        for (int t = 0; t < maxlen; ++t) {
            const int buf  = t & 1;
            const bool more = (t + 1 < maxlen);
            if (pf_th && more) {
#pragma unroll
                for (int i = 0; i < 3; ++i) {
                    int p  = pt + 128 * i;
                    int sp = (p >= 192) ? 1 : 0;
                    int c2 = p - sp * 192;
                    int bsp = sp ? b_s1 : b_s0;
                    int lsp = sp ? len1 : len0;
                    if (t + 1 < lsp) {
                        const float* gsrc = g_xpc + ((size_t)bsp * TSEQ + (lsp - 2 - t)) * NC + coff + 2 * c2;
                        cp8(sptr(&xsm[buf ^ 1][sp * 384 + 2 * c2]), gsrc);
                    }
                }
                CP_COMMIT();
            }

            ull acc0 = pk2(brec, 0.f);
            ull acc1 = pk2(brec, 0.f);
#pragma unroll
            for (int q = 0; q < 32; ++q) {
                ull u0 = u2[2 * q], u1 = u2[2 * q + 1];
                ulonglong2 h0 = *(const ulonglong2*)&hsm[0][4 * q];
                ulonglong2 h1 = *(const ulonglong2*)&hsm[1][4 * q];
                ffma2(acc0, u0, h0.x);
                ffma2(acc0, u1, h0.y);
                ffma2(acc1, u0, h1.x);
                ffma2(acc1, u1, h1.y);
            }
            { float2 f = upk2(acc0); rps[0][j] = f.x + f.y; }
            { float2 f = upk2(acc1); rps[1][j] = f.x + f.y; }

            if (pf_th) { if (more) { CP_WAIT1(); } else { CP_WAIT0(); } }
            __syncthreads();

            if (gate_th) {
                float h_old = hsm[s][d];
                float hn = h_old;
                if (t < len_g) {
                    float xz = xsm[buf][s * 384 + d];
                    float xr = xsm[buf][s * 384 + 128 + d];
                    float xh = xsm[buf][s * 384 + 256 + d];
                    float zg = sigm(xz + rps[s][d]);
                    float rg = sigm(xr + rps[s][128 + d]);
                    float hh = ftanh(xh + rg * rps[s][256 + d]);
                    hn = zg * h_old + (1.f - zg) * hh;
                }
                hsm[s][d] = hn;
                stp[0] = hn;
            }
            __syncthreads();
            stp += DDIM;
        }
        const int tail = TSEQ - maxlen;
        for (int idx = j; idx < tail * 256; idx += 384) {
            int dd = idx & 127;
            int ss = (idx >> 7) & 1;
            int tt = idx >> 8;
            int bb = ss ? b_s1 : b_s0;
            st[(size_t)bb * TD + (size_t)(maxlen + tt) * DDIM + dd] = hsm[ss][dd];
        }
        __syncthreads();
    }
}

// ============================================================================
// Kernel 3a: alpha weights (unchanged); also zeros out for k_beta's atomics.
// ============================================================================
__global__ void __launch_bounds__(128, 4) k_alpha(
    const float* __restrict__ W_alpha, const float* __restrict__ b_alpha,
    float* __restrict__ out)
{
    __shared__ float e_s[TSEQ];
    __shared__ float red[4];
    __shared__ float scal[2];

    const int b    = blockIdx.x;
    const int tid  = threadIdx.x;
    const int lane = tid & 31, w = tid >> 5;

    out[(size_t)b * DDIM + tid] = 0.f;

    float4 wa = *(const float4*)&W_alpha[lane * 4];
    const float b_a = b_alpha[0];
    const float* gbase = g_g + (size_t)b * TD;
    for (int tt = 0; tt < 128; ++tt) {
        int t = tt * 4 + w;
        float4 gv = *(const float4*)&gbase[(size_t)t * DDIM + lane * 4];
        float sum = gv.x * wa.x + gv.y * wa.y + gv.z * wa.z + gv.w * wa.w;
#pragma unroll
        for (int o = 16; o > 0; o >>= 1) sum += __shfl_xor_sync(0xffffffffu, sum, o);
        if (lane == 0) e_s[t] = sum + b_a;
    }
    __syncthreads();

    float m = -1e30f;
    for (int i = tid; i < TSEQ; i += 128) m = fmaxf(m, e_s[i]);
#pragma unroll
    for (int o = 16; o > 0; o >>= 1) m = fmaxf(m, __shfl_xor_sync(0xffffffffu, m, o));
    if (lane == 0) red[w] = m;
    __syncthreads();
    if (tid == 0) scal[0] = fmaxf(fmaxf(red[0], red[1]), fmaxf(red[2], red[3]));
    __syncthreads();
    const float M = scal[0];
    float ss = 0.f;
    for (int i = tid; i < TSEQ; i += 128) { float p = __expf(e_s[i] - M); e_s[i] = p; ss += p; }
#pragma unroll
    for (int o = 16; o > 0; o >>= 1) ss += __shfl_xor_sync(0xffffffffu, ss, o);
    if (lane == 0) red[w] = ss;
    __syncthreads();
    if (tid == 0) scal[1] = red[0] + red[1] + red[2] + red[3];
    __syncthreads();
    const float Sinv = 1.f / scal[1];
    for (int i = tid; i < TSEQ; i += 128)
        g_alpha[(size_t)b * TSEQ + i] = e_s[i] * Sinv;
}

// ============================================================================
// Kernel 3b: beta GEMM via 3xTF32 mma.sync, fused alpha*tanh(.)*x epilogue.
// float4 staging loads. grid 2048.
// ============================================================================
__global__ void __launch_bounds__(256) k_beta(
    const float* __restrict__ x,
    const float* __restrict__ W_beta, const float* __restrict__ b_beta,
    float* __restrict__ out)
{
    extern __shared__ __align__(16) unsigned smu[];
    unsigned* XH = smu;                  // [64][68]  (h tile)
    unsigned* XL = XH + 64 * 68;
    unsigned* WH = XL + 64 * 68;         // [64][132] (W_beta tile)
    unsigned* WL = WH + 64 * 132;

    const int b   = blockIdx.x >> 3;
    const int t0  = (blockIdx.x & 7) << 6;

    const int tid  = threadIdx.x;
    const int lane = tid & 31, w = tid >> 5;
    const int wr = w >> 2, wc = w & 3;
    const int r  = lane >> 2, cq = lane & 3;

    float acc[2][4][4];
#pragma unroll
    for (int m = 0; m < 2; m++)
#pragma unroll
        for (int n = 0; n < 4; n++)
#pragma unroll
            for (int e = 0; e < 4; e++) acc[m][n][e] = 0.f;

    const float* hbase = g_h + (size_t)b * TD;
    for (int kc = 0; kc < 2; ++kc) {
        __syncthreads();
#pragma unroll
        for (int l = 0; l < 4; ++l) {
            int idx = tid + l * 256;
            int tt = idx >> 4, k4 = (idx & 15) << 2;
            float4 v = *(const float4*)&hbase[(size_t)(t0 + tt) * DDIM + kc * 64 + k4];
            const float* pv = (const float*)&v;
#pragma unroll
            for (int e = 0; e < 4; ++e) {
                unsigned hi = f2tf(pv[e]);
                XH[tt * 68 + k4 + e] = hi;
                XL[tt * 68 + k4 + e] = f2tf(pv[e] - __uint_as_float(hi));
            }
        }
#pragma unroll
        for (int l = 0; l < 8; ++l) {
            int idx = tid + l * 256;
            int kk = idx >> 5, j4 = (idx & 31) << 2;
            float4 v = *(const float4*)&W_beta[(size_t)(kc * 64 + kk) * DDIM + j4];
            const float* pv = (const float*)&v;
#pragma unroll
            for (int e = 0; e < 4; ++e) {
                unsigned hi = f2tf(pv[e]);
                WH[kk * 132 + j4 + e] = hi;
                WL[kk * 132 + j4 + e] = f2tf(pv[e] - __uint_as_float(hi));
            }
        }
        __syncthreads();
#pragma unroll
        for (int ks = 0; ks < 8; ++ks) {
            const int k0 = ks * 8;
            unsigned bh[4][2], bl[4][2];
#pragma unroll
            for (int n = 0; n < 4; ++n) {
                int nn = wc * 32 + n * 8 + r;
                bh[n][0] = WH[(k0 + cq) * 132 + nn];
                bh[n][1] = WH[(k0 + 4 + cq) * 132 + nn];
                bl[n][0] = WL[(k0 + cq) * 132 + nn];
                bl[n][1] = WL[(k0 + 4 + cq) * 132 + nn];
            }
#pragma unroll
            for (int m = 0; m < 2; ++m) {
                int rr = wr * 32 + m * 16 + r;
                unsigned ah0 = XH[rr * 68 + k0 + cq];
                unsigned ah1 = XH[(rr + 8) * 68 + k0 + cq];
                unsigned ah2 = XH[rr * 68 + k0 + 4 + cq];
                unsigned ah3 = XH[(rr + 8) * 68 + k0 + 4 + cq];
                unsigned al0 = XL[rr * 68 + k0 + cq];
                unsigned al1 = XL[(rr + 8) * 68 + k0 + cq];
                unsigned al2 = XL[rr * 68 + k0 + 4 + cq];
                unsigned al3 = XL[(rr + 8) * 68 + k0 + 4 + cq];
#pragma unroll
                for (int n = 0; n < 4; ++n) {
                    mma8(acc[m][n], ah0, ah1, ah2, ah3, bh[n][0], bh[n][1]);
                    mma8(acc[m][n], ah0, ah1, ah2, ah3, bl[n][0], bl[n][1]);
                    mma8(acc[m][n], al0, al1, al2, al3, bh[n][0], bh[n][1]);
                }
            }
        }
    }

    // fused epilogue: csum[col] = sum_rows alpha_t * tanh(acc + b_beta[col]) * x[t][col]
    float csum[8];
#pragma unroll
    for (int e = 0; e < 8; ++e) csum[e] = 0.f;

#pragma unroll
    for (int m = 0; m < 2; ++m) {
#pragma unroll
        for (int p = 0; p < 2; ++p) {
            int t = t0 + wr * 32 + m * 16 + r + p * 8;
            float alv = g_alpha[(size_t)b * TSEQ + t];
            const float* xrow = &x[((size_t)b * TSEQ + t) * DDIM];
#pragma unroll
            for (int n = 0; n < 4; ++n) {
                int ccl = wc * 32 + n * 8 + 2 * cq;
                float2 bi = *(const float2*)&b_beta[ccl];
                float2 xv = *(const float2*)&xrow[ccl];
                float v0 = ftanh(acc[m][n][2 * p]     + bi.x);
                float v1 = ftanh(acc[m][n][2 * p + 1] + bi.y);
                csum[2 * n]     += alv * v0 * xv.x;
                csum[2 * n + 1] += alv * v1 * xv.y;
            }
        }
    }
#pragma unroll
    for (int o = 4; o <= 16; o <<= 1)
#pragma unroll
        for (int e = 0; e < 8; ++e)
            csum[e] += __shfl_xor_sync(0xffffffffu, csum[e], o);

    __syncthreads();
    float* part = (float*)smu;
    if (r == 0) {
#pragma unroll
        for (int n = 0; n < 4; ++n) {
            part[wr * DDIM + wc * 32 + n * 8 + 2 * cq]     = csum[2 * n];
            part[wr * DDIM + wc * 32 + n * 8 + 2 * cq + 1] = csum[2 * n + 1];
        }
    }
    __syncthreads();
    if (tid < DDIM)
        atomicAdd(&out[(size_t)b * DDIM + tid], part[tid] + part[DDIM + tid]);
}

// ============================================================================
extern "C" void kernel_launch(void* const* d_in, const int* in_sizes, int n_in,
                              void* d_out, int out_size)
{
    const float* x       = (const float*)d_in[0];
    const int*   lengths = (const int*)  d_in[1];
    const float* Wa      = (const float*)d_in[2];
    const float* Ua      = (const float*)d_in[3];
    const float* ba_in   = (const float*)d_in[4];
    const float* ba_rec  = (const float*)d_in[5];
    const float* Wb      = (const float*)d_in[6];
    const float* Ub      = (const float*)d_in[7];
    const float* bb_in   = (const float*)d_in[8];
    const float* bb_rec  = (const float*)d_in[9];
    const float* W_alpha = (const float*)d_in[10];
    const float* b_alpha = (const float*)d_in[11];
    const float* W_beta  = (const float*)d_in[12];
    const float* b_beta  = (const float*)d_in[13];
    float* out = (float*)d_out;

    cudaFuncSetAttribute(k_xp,   cudaFuncAttributeMaxDynamicSharedMemorySize, TF_SMEM);
    cudaFuncSetAttribute(k_beta, cudaFuncAttributeMaxDynamicSharedMemorySize, TF_SMEM);

    k_sort <<<1, BATCH>>>(lengths);
    k_xp   <<<dim3(2048, 6), 256, TF_SMEM>>>(x, lengths, Wa, ba_in, Wb, bb_in);
    k_gru  <<<148, 384>>>(lengths, Ua, ba_rec, Ub, bb_rec);
    k_alpha<<<256, 128>>>(W_alpha, b_alpha, out);
    k_beta <<<2048, 256, TF_SMEM>>>(x, W_beta, b_beta, out);
    k_nop  <<<1, 32>>>();   // shifts ncu's captured launch onto k_gru
    (void)in_sizes; (void)n_in; (void)out_size;
}